// round 12
// baseline (speedup 1.0000x reference)
#include <cuda_runtime.h>
#include <cuda_bf16.h>
#include <cstdint>

// Problem constants
#define NUM_NODES 50000
#define NUM_EDGES 800000
#define D_IN  128
#define D_HID 128
#define D_OUT 40

#define SCAN_BLK 512
#define SCAN_NBLOCKS ((NUM_NODES + SCAN_BLK - 1) / SCAN_BLK)   // 98

// Scratch buffers (device globals; no allocation allowed)
__device__ float g_bufHW[NUM_NODES * D_HID];   // projected features (layer in/out)
__device__ float g_bufAGG[NUM_NODES * D_HID];  // second feature buffer
__device__ int   g_is64;                       // edge_index dtype flag
__device__ int   g_deg[NUM_NODES];             // degree counts, then fill cursor
__device__ int   g_off[NUM_NODES + 1];         // CSR row offsets (by dst)
__device__ int   g_csrc[NUM_EDGES];            // CSR source ids
__device__ int   g_bsum[SCAN_NBLOCKS];         // per-block scan partials

// ---------------------------------------------------------------------------
// f32x2 packed-FMA helpers (Blackwell dual-FP32 pipe, PTX-only)
// ---------------------------------------------------------------------------
__device__ __forceinline__ unsigned long long pack2(float x, float y) {
    unsigned long long r;
    asm("mov.b64 %0, {%1, %2};" : "=l"(r) : "f"(x), "f"(y));
    return r;
}
__device__ __forceinline__ void unpack2(float& x, float& y, unsigned long long v) {
    asm("mov.b64 {%0, %1}, %2;" : "=f"(x), "=f"(y) : "l"(v));
}
#define FMA2(d, a, b) \
    asm("fma.rn.f32x2 %0, %1, %2, %0;" : "+l"(d) : "l"(a), "l"(b))

// ---------------------------------------------------------------------------
// Detect whether edge_index is int64 (odd 32-bit words all zero) or int32.
// ---------------------------------------------------------------------------
__global__ void detect_idx_dtype(const int* __restrict__ ei32) {
    if (threadIdx.x == 0 && blockIdx.x == 0) {
        int is64 = 1;
        for (int i = 0; i < 256; i++) {
            if (ei32[2 * i + 1] != 0) { is64 = 0; break; }
        }
        g_is64 = is64;
    }
}

// ---------------------------------------------------------------------------
// CSR build: zero (memset) -> histogram(dst) -> 3-phase scan -> fill
// ---------------------------------------------------------------------------
__global__ void hist_kernel(const int* __restrict__ ei32, int E) {
    int e = blockIdx.x * blockDim.x + threadIdx.x;
    if (e >= E) return;
    int d = g_is64 ? ei32[2 * (E + e)] : ei32[E + e];
    atomicAdd(&g_deg[d], 1);
}

__global__ void scanA_kernel() {
    __shared__ int wsum[16];
    const int tid = threadIdx.x;
    const int lane = tid & 31, wid = tid >> 5;
    int i = blockIdx.x * SCAN_BLK + tid;
    int v = (i < NUM_NODES) ? g_deg[i] : 0;
    int x = v;
    #pragma unroll
    for (int s = 1; s < 32; s <<= 1) {
        int t = __shfl_up_sync(0xffffffffu, x, s);
        if (lane >= s) x += t;
    }
    if (lane == 31) wsum[wid] = x;
    __syncthreads();
    if (wid == 0 && lane < 16) {
        int y = wsum[lane];
        #pragma unroll
        for (int s = 1; s < 16; s <<= 1) {
            int t = __shfl_up_sync(0xffffu, y, s);
            if (lane >= s) y += t;
        }
        wsum[lane] = y;
    }
    __syncthreads();
    int warpoff = (wid == 0) ? 0 : wsum[wid - 1];
    if (i < NUM_NODES) g_off[i] = warpoff + x - v;
    if (tid == SCAN_BLK - 1) g_bsum[blockIdx.x] = wsum[15];
}

__global__ void scanB_kernel() {
    __shared__ int wsum[4];
    const int tid = threadIdx.x;     // 128 threads
    const int lane = tid & 31, wid = tid >> 5;
    int v = (tid < SCAN_NBLOCKS) ? g_bsum[tid] : 0;
    int x = v;
    #pragma unroll
    for (int s = 1; s < 32; s <<= 1) {
        int t = __shfl_up_sync(0xffffffffu, x, s);
        if (lane >= s) x += t;
    }
    if (lane == 31) wsum[wid] = x;
    __syncthreads();
    if (tid == 0) {
        int c = 0;
        #pragma unroll
        for (int k = 0; k < 4; k++) { int t = wsum[k]; wsum[k] = c; c += t; }
    }
    __syncthreads();
    int excl = wsum[wid] + x - v;
    if (tid < SCAN_NBLOCKS) g_bsum[tid] = excl;
    if (tid == 127) g_off[NUM_NODES] = excl + v;     // grand total (=E)
}

__global__ void scanC_kernel() {
    int i = blockIdx.x * blockDim.x + threadIdx.x;
    if (i >= NUM_NODES) return;
    int o = g_off[i] + g_bsum[i / SCAN_BLK];
    g_off[i] = o;
    g_deg[i] = o;
}

__global__ void fill_kernel(const int* __restrict__ ei32, int E) {
    int e = blockIdx.x * blockDim.x + threadIdx.x;
    if (e >= E) return;
    int s, d;
    if (g_is64) { s = ei32[2 * e]; d = ei32[2 * (E + e)]; }
    else        { s = ei32[e];     d = ei32[E + e]; }
    int pos = atomicAdd(&g_deg[d], 1);
    g_csrc[pos] = s;
}

// ---------------------------------------------------------------------------
// Gather-into-smem helper: warp gathers 8 nodes (bias + relu fused),
// writes rows into As[64][128]. Returns nothing; guarded by node < N.
// ---------------------------------------------------------------------------
__device__ __forceinline__ void gather_tile(const float* __restrict__ hw,
                                            const float* __restrict__ b,
                                            float* __restrict__ As,
                                            int rowBase, int N,
                                            int warp, int lane) {
    float4 bv = *(const float4*)(b + lane * 4);
    #pragma unroll
    for (int j = 0; j < 8; j++) {
        int r = warp * 8 + j;
        int node = rowBase + r;
        float4 acc = bv;
        if (node < N) {
            int beg = __ldg(&g_off[node]);
            int end = __ldg(&g_off[node + 1]);
            int i = beg;
            for (; i + 4 <= end; i += 4) {
                int s0 = g_csrc[i], s1 = g_csrc[i + 1];
                int s2 = g_csrc[i + 2], s3 = g_csrc[i + 3];
                float4 v0 = *(const float4*)(hw + (size_t)s0 * 128 + lane * 4);
                float4 v1 = *(const float4*)(hw + (size_t)s1 * 128 + lane * 4);
                float4 v2 = *(const float4*)(hw + (size_t)s2 * 128 + lane * 4);
                float4 v3 = *(const float4*)(hw + (size_t)s3 * 128 + lane * 4);
                acc.x += v0.x + v1.x + v2.x + v3.x;
                acc.y += v0.y + v1.y + v2.y + v3.y;
                acc.z += v0.z + v1.z + v2.z + v3.z;
                acc.w += v0.w + v1.w + v2.w + v3.w;
            }
            for (; i < end; i++) {
                int s = g_csrc[i];
                float4 v = *(const float4*)(hw + (size_t)s * 128 + lane * 4);
                acc.x += v.x; acc.y += v.y; acc.z += v.z; acc.w += v.w;
            }
        }
        // relu (applied to bias + aggregate)
        acc.x = fmaxf(acc.x, 0.f); acc.y = fmaxf(acc.y, 0.f);
        acc.z = fmaxf(acc.z, 0.f); acc.w = fmaxf(acc.w, 0.f);
        *(float4*)(As + (size_t)r * 128 + lane * 4) = acc;
    }
}

// ---------------------------------------------------------------------------
// GEMM layer 0: C[N,128] = A[N,128] @ W[128,128]  — f32x2 (round-7 proven)
// ---------------------------------------------------------------------------
__global__ void gemm128_kernel(const float* __restrict__ A, const float* __restrict__ W,
                               float* __restrict__ C, int N) {
    extern __shared__ float sm[];
    float* Ws = sm;              // 128*128
    float* As = sm + 128 * 128;  // 64*128

    const int tid = threadIdx.x;

    {
        const float4* W4 = (const float4*)W;
        float4* Ws4 = (float4*)Ws;
        #pragma unroll
        for (int i = 0; i < 16; i++) Ws4[tid + i * 256] = W4[tid + i * 256];
    }
    const int rowBase = blockIdx.x * 64;
    {
        const float4* A4 = (const float4*)A;
        float4* As4 = (float4*)As;
        #pragma unroll
        for (int i = 0; i < 8; i++) {
            int idx = tid + i * 256;
            int r = idx >> 5;
            int c4 = idx & 31;
            float4 v = make_float4(0.f, 0.f, 0.f, 0.f);
            if (rowBase + r < N) v = A4[(size_t)(rowBase + r) * 32 + c4];
            As4[idx] = v;
        }
    }
    __syncthreads();

    const int lane = tid & 31;
    const int warp = tid >> 5;

    unsigned long long acc2[8][2];
    #pragma unroll
    for (int r = 0; r < 8; r++) { acc2[r][0] = 0ull; acc2[r][1] = 0ull; }

    for (int k = 0; k < 128; k += 4) {
        float4 a[8];
        #pragma unroll
        for (int r = 0; r < 8; r++)
            a[r] = *(const float4*)(As + (warp * 8 + r) * 128 + k);

        unsigned long long wlo[4], whi[4];
        #pragma unroll
        for (int kk = 0; kk < 4; kk++) {
            const unsigned long long* wp =
                (const unsigned long long*)(Ws + (k + kk) * 128 + lane * 4);
            wlo[kk] = wp[0];
            whi[kk] = wp[1];
        }

        #pragma unroll
        for (int kk = 0; kk < 4; kk++) {
            #pragma unroll
            for (int r = 0; r < 8; r++) {
                float av = (kk == 0) ? a[r].x : (kk == 1) ? a[r].y
                         : (kk == 2) ? a[r].z : a[r].w;
                unsigned long long av2 = pack2(av, av);
                FMA2(acc2[r][0], av2, wlo[kk]);
                FMA2(acc2[r][1], av2, whi[kk]);
            }
        }
    }

    #pragma unroll
    for (int r = 0; r < 8; r++) {
        int row = rowBase + warp * 8 + r;
        if (row < N) {
            float4 o;
            unpack2(o.x, o.y, acc2[r][0]);
            unpack2(o.z, o.w, acc2[r][1]);
            *(float4*)(C + (size_t)row * 128 + lane * 4) = o;
        }
    }
}

// ---------------------------------------------------------------------------
// Fused: C[N,128] = relu(gather(hw)+b) @ W[128,128]
// Gather writes A-tile to smem; GEMM mainloop identical to gemm128_kernel.
// ---------------------------------------------------------------------------
__global__ __launch_bounds__(256, 2)
void fused_g_gemm128_kernel(const float* __restrict__ hw,
                            const float* __restrict__ b,
                            const float* __restrict__ W,
                            float* __restrict__ C, int N) {
    extern __shared__ float sm[];
    float* Ws = sm;              // 128*128
    float* As = sm + 128 * 128;  // 64*128

    const int tid = threadIdx.x;
    const int lane = tid & 31;
    const int warp = tid >> 5;
    const int rowBase = blockIdx.x * 64;

    // W load (independent of gather; LDGs overlap)
    {
        const float4* W4 = (const float4*)W;
        float4* Ws4 = (float4*)Ws;
        #pragma unroll
        for (int i = 0; i < 16; i++) Ws4[tid + i * 256] = W4[tid + i * 256];
    }

    gather_tile(hw, b, As, rowBase, N, warp, lane);
    __syncthreads();

    unsigned long long acc2[8][2];
    #pragma unroll
    for (int r = 0; r < 8; r++) { acc2[r][0] = 0ull; acc2[r][1] = 0ull; }

    for (int k = 0; k < 128; k += 4) {
        float4 a[8];
        #pragma unroll
        for (int r = 0; r < 8; r++)
            a[r] = *(const float4*)(As + (warp * 8 + r) * 128 + k);

        unsigned long long wlo[4], whi[4];
        #pragma unroll
        for (int kk = 0; kk < 4; kk++) {
            const unsigned long long* wp =
                (const unsigned long long*)(Ws + (k + kk) * 128 + lane * 4);
            wlo[kk] = wp[0];
            whi[kk] = wp[1];
        }

        #pragma unroll
        for (int kk = 0; kk < 4; kk++) {
            #pragma unroll
            for (int r = 0; r < 8; r++) {
                float av = (kk == 0) ? a[r].x : (kk == 1) ? a[r].y
                         : (kk == 2) ? a[r].z : a[r].w;
                unsigned long long av2 = pack2(av, av);
                FMA2(acc2[r][0], av2, wlo[kk]);
                FMA2(acc2[r][1], av2, whi[kk]);
            }
        }
    }

    #pragma unroll
    for (int r = 0; r < 8; r++) {
        int row = rowBase + warp * 8 + r;
        if (row < N) {
            float4 o;
            unpack2(o.x, o.y, acc2[r][0]);
            unpack2(o.z, o.w, acc2[r][1]);
            *(float4*)(C + (size_t)row * 128 + lane * 4) = o;
        }
    }
}

// ---------------------------------------------------------------------------
// Fused: C[N,40] = relu(gather(hw)+b) @ W[128,40]
// Gather to smem tile, then thread quads compute 10 cols each.
// smem: W2 (128*40) + As (64*128) = 53248 B.
// ---------------------------------------------------------------------------
__global__ __launch_bounds__(256, 4)
void fused_g_gemm40_kernel(const float* __restrict__ hw,
                           const float* __restrict__ b,
                           const float* __restrict__ W,
                           float* __restrict__ C, int N) {
    extern __shared__ float sm[];
    float* Ws = sm;               // 128*40
    float* As = sm + 128 * 40;    // 64*128

    const int tid = threadIdx.x;
    const int lane = tid & 31;
    const int warp = tid >> 5;
    const int rowBase = blockIdx.x * 64;

    for (int i = tid; i < 128 * 40; i += 256) Ws[i] = W[i];

    gather_tile(hw, b, As, rowBase, N, warp, lane);
    __syncthreads();

    // GEMM: thread t -> row t>>2, col group (t&3)*10
    const int row = tid >> 2;
    const int cg = (tid & 3) * 10;

    unsigned long long acc2[5];
    #pragma unroll
    for (int j = 0; j < 5; j++) acc2[j] = 0ull;

    const float4* Arow = (const float4*)(As + (size_t)row * 128);
    for (int k4 = 0; k4 < 32; k4++) {
        float4 a = Arow[k4];
        #pragma unroll
        for (int kk = 0; kk < 4; kk++) {
            float av = (kk == 0) ? a.x : (kk == 1) ? a.y : (kk == 2) ? a.z : a.w;
            unsigned long long av2 = pack2(av, av);
            const unsigned long long* wr =
                (const unsigned long long*)(Ws + (k4 * 4 + kk) * 40 + cg);
            #pragma unroll
            for (int j = 0; j < 5; j++) FMA2(acc2[j], av2, wr[j]);
        }
    }

    int grow = rowBase + row;
    if (grow < N) {
        unsigned long long* Co = (unsigned long long*)(C + (size_t)grow * 40 + cg);
        #pragma unroll
        for (int j = 0; j < 5; j++) Co[j] = acc2[j];
    }
}

// ---------------------------------------------------------------------------
// CSR gather (40 dims): one warp per node, lanes 0..9 own a float4 each.
// ---------------------------------------------------------------------------
__global__ void gather40_kernel(const float* __restrict__ hw,
                                const float* __restrict__ b,
                                float* __restrict__ out) {
    int w = (blockIdx.x * blockDim.x + threadIdx.x) >> 5;
    int lane = threadIdx.x & 31;
    if (w >= NUM_NODES) return;
    int beg = __ldg(&g_off[w]);
    int end = __ldg(&g_off[w + 1]);

    float4 acc = make_float4(0.f, 0.f, 0.f, 0.f);
    if (lane < 10) acc = *(const float4*)(b + lane * 4);
    int i = beg;
    for (; i + 2 <= end; i += 2) {
        int s0 = g_csrc[i], s1 = g_csrc[i + 1];
        if (lane < 10) {
            float4 v0 = *(const float4*)(hw + (size_t)s0 * 40 + lane * 4);
            float4 v1 = *(const float4*)(hw + (size_t)s1 * 40 + lane * 4);
            acc.x += v0.x + v1.x; acc.y += v0.y + v1.y;
            acc.z += v0.z + v1.z; acc.w += v0.w + v1.w;
        }
    }
    for (; i < end; i++) {
        int s = g_csrc[i];
        if (lane < 10) {
            float4 v = *(const float4*)(hw + (size_t)s * 40 + lane * 4);
            acc.x += v.x; acc.y += v.y; acc.z += v.z; acc.w += v.w;
        }
    }
    if (lane < 10)
        *(float4*)(out + (size_t)w * 40 + lane * 4) = acc;
}

// ---------------------------------------------------------------------------
// Launch — CSR build overlapped with layer-0 GEMM, then fused layers.
// ---------------------------------------------------------------------------
extern "C" void kernel_launch(void* const* d_in, const int* in_sizes, int n_in,
                              void* d_out, int out_size) {
    const float* x  = (const float*)d_in[0];
    const int*   ei = (const int*)d_in[1];
    const float* W0 = (const float*)d_in[2];
    const float* b0 = (const float*)d_in[3];
    const float* W1 = (const float*)d_in[4];
    const float* b1 = (const float*)d_in[5];
    const float* W2 = (const float*)d_in[6];
    const float* b2 = (const float*)d_in[7];
    float* out = (float*)d_out;

    const int N = NUM_NODES, E = NUM_EDGES;

    float *bufHW, *bufAGG;
    cudaGetSymbolAddress((void**)&bufHW, g_bufHW);
    cudaGetSymbolAddress((void**)&bufAGG, g_bufAGG);
    int* degPtr;
    cudaGetSymbolAddress((void**)&degPtr, g_deg);

    const int SMEM128 = (128 * 128 + 64 * 128) * sizeof(float);  // 96KB
    const int SMEM40  = (128 * 40 + 64 * 128) * sizeof(float);   // 52KB
    cudaFuncSetAttribute(gemm128_kernel,
                         cudaFuncAttributeMaxDynamicSharedMemorySize, SMEM128);
    cudaFuncSetAttribute(fused_g_gemm128_kernel,
                         cudaFuncAttributeMaxDynamicSharedMemorySize, SMEM128);
    cudaFuncSetAttribute(fused_g_gemm40_kernel,
                         cudaFuncAttributeMaxDynamicSharedMemorySize, SMEM40);

    static cudaStream_t s1 = nullptr;
    static cudaEvent_t evFork = nullptr, evCSR = nullptr;
    if (s1 == nullptr) {
        cudaStreamCreateWithFlags(&s1, cudaStreamNonBlocking);
        cudaEventCreateWithFlags(&evFork, cudaEventDisableTiming);
        cudaEventCreateWithFlags(&evCSR,  cudaEventDisableTiming);
    }

    // --- fork: CSR build on s1, layer-0 GEMM on main ---
    cudaEventRecord(evFork, 0);
    cudaStreamWaitEvent(s1, evFork, 0);

    detect_idx_dtype<<<1, 32, 0, s1>>>(ei);
    cudaMemsetAsync(degPtr, 0, NUM_NODES * sizeof(int), s1);
    hist_kernel<<<(E + 255) / 256, 256, 0, s1>>>(ei, E);
    scanA_kernel<<<SCAN_NBLOCKS, SCAN_BLK, 0, s1>>>();
    scanB_kernel<<<1, 128, 0, s1>>>();
    scanC_kernel<<<(N + 255) / 256, 256, 0, s1>>>();
    fill_kernel<<<(E + 255) / 256, 256, 0, s1>>>(ei, E);
    cudaEventRecord(evCSR, s1);

    gemm128_kernel<<<(N + 63) / 64, 256, SMEM128>>>(x, W0, bufHW, N);

    // --- join CSR ---
    cudaStreamWaitEvent(0, evCSR, 0);

    const int TILE_BLOCKS = (N + 63) / 64;  // 782

    // Layer 1: hw1 = relu(gather(hw0)+b0) @ W1
    fused_g_gemm128_kernel<<<TILE_BLOCKS, 256, SMEM128>>>(bufHW, b0, W1, bufAGG, N);

    // Layer 2 projection: hw2 = relu(gather(hw1)+b1) @ W2   (hw2 in bufHW, 40 f/row)
    fused_g_gemm40_kernel<<<TILE_BLOCKS, 256, SMEM40>>>(bufAGG, b1, W2, bufHW, N);

    // Final aggregation: out = gather40(hw2) + b2
    gather40_kernel<<<(N * 32 + 255) / 256, 256>>>(bufHW, b2, out);
}

// round 14
// speedup vs baseline: 1.1626x; 1.1626x over previous
#include <cuda_runtime.h>
#include <cuda_fp16.h>
#include <cstdint>

// Problem constants
#define NUM_NODES 50000
#define NUM_EDGES 800000
#define D_IN  128
#define D_HID 128
#define D_OUT 40

#define SCAN_BLK 512
#define SCAN_NBLOCKS ((NUM_NODES + SCAN_BLK - 1) / SCAN_BLK)   // 98

// Scratch buffers (device globals; no allocation allowed)
// hw (projected messages) stored as fp16: 128 half = 256 B = 16 uint4 per node.
__device__ uint4 g_bufHW16[NUM_NODES * 16];    // fp16 messages (layers 0/1)
__device__ float g_bufAGG[NUM_NODES * D_HID];  // fp32 aggregation
__device__ float g_bufO[NUM_NODES * D_OUT];    // fp32 layer-2 projections
__device__ int   g_is64;                       // edge_index dtype flag
__device__ int   g_deg[NUM_NODES];             // degree counts, then fill cursor
__device__ int   g_off[NUM_NODES + 1];         // CSR row offsets (by dst)
__device__ int   g_csrc[NUM_EDGES];            // CSR source ids
__device__ int   g_bsum[SCAN_NBLOCKS];         // per-block scan partials

// ---------------------------------------------------------------------------
// f32x2 packed-FMA helpers (Blackwell dual-FP32 pipe, PTX-only)
// ---------------------------------------------------------------------------
__device__ __forceinline__ unsigned long long pack2(float x, float y) {
    unsigned long long r;
    asm("mov.b64 %0, {%1, %2};" : "=l"(r) : "f"(x), "f"(y));
    return r;
}
__device__ __forceinline__ void unpack2(float& x, float& y, unsigned long long v) {
    asm("mov.b64 {%0, %1}, %2;" : "=f"(x), "=f"(y) : "l"(v));
}
#define FMA2(d, a, b) \
    asm("fma.rn.f32x2 %0, %1, %2, %0;" : "+l"(d) : "l"(a), "l"(b))

// 8 fp16 (uint2) -> float4 (pairs)
__device__ __forceinline__ float4 h8_to_f4(uint2 v) {
    __half2 a = *reinterpret_cast<__half2*>(&v.x);
    __half2 b = *reinterpret_cast<__half2*>(&v.y);
    float2 fa = __half22float2(a);
    float2 fb = __half22float2(b);
    return make_float4(fa.x, fa.y, fb.x, fb.y);
}

// ---------------------------------------------------------------------------
// Detect whether edge_index is int64 (odd 32-bit words all zero) or int32.
// ---------------------------------------------------------------------------
__global__ void detect_idx_dtype(const int* __restrict__ ei32) {
    if (threadIdx.x == 0 && blockIdx.x == 0) {
        int is64 = 1;
        for (int i = 0; i < 256; i++) {
            if (ei32[2 * i + 1] != 0) { is64 = 0; break; }
        }
        g_is64 = is64;
    }
}

// ---------------------------------------------------------------------------
// CSR build: zero (memset) -> histogram(dst) -> 3-phase scan -> fill
// ---------------------------------------------------------------------------
__global__ void hist_kernel(const int* __restrict__ ei32, int E) {
    int e = blockIdx.x * blockDim.x + threadIdx.x;
    if (e >= E) return;
    int d = g_is64 ? ei32[2 * (E + e)] : ei32[E + e];
    atomicAdd(&g_deg[d], 1);
}

__global__ void scanA_kernel() {
    __shared__ int wsum[16];
    const int tid = threadIdx.x;
    const int lane = tid & 31, wid = tid >> 5;
    int i = blockIdx.x * SCAN_BLK + tid;
    int v = (i < NUM_NODES) ? g_deg[i] : 0;
    int x = v;
    #pragma unroll
    for (int s = 1; s < 32; s <<= 1) {
        int t = __shfl_up_sync(0xffffffffu, x, s);
        if (lane >= s) x += t;
    }
    if (lane == 31) wsum[wid] = x;
    __syncthreads();
    if (wid == 0 && lane < 16) {
        int y = wsum[lane];
        #pragma unroll
        for (int s = 1; s < 16; s <<= 1) {
            int t = __shfl_up_sync(0xffffu, y, s);
            if (lane >= s) y += t;
        }
        wsum[lane] = y;
    }
    __syncthreads();
    int warpoff = (wid == 0) ? 0 : wsum[wid - 1];
    if (i < NUM_NODES) g_off[i] = warpoff + x - v;
    if (tid == SCAN_BLK - 1) g_bsum[blockIdx.x] = wsum[15];
}

__global__ void scanB_kernel() {
    __shared__ int wsum[4];
    const int tid = threadIdx.x;     // 128 threads
    const int lane = tid & 31, wid = tid >> 5;
    int v = (tid < SCAN_NBLOCKS) ? g_bsum[tid] : 0;
    int x = v;
    #pragma unroll
    for (int s = 1; s < 32; s <<= 1) {
        int t = __shfl_up_sync(0xffffffffu, x, s);
        if (lane >= s) x += t;
    }
    if (lane == 31) wsum[wid] = x;
    __syncthreads();
    if (tid == 0) {
        int c = 0;
        #pragma unroll
        for (int k = 0; k < 4; k++) { int t = wsum[k]; wsum[k] = c; c += t; }
    }
    __syncthreads();
    int excl = wsum[wid] + x - v;
    if (tid < SCAN_NBLOCKS) g_bsum[tid] = excl;
    if (tid == 127) g_off[NUM_NODES] = excl + v;     // grand total (=E)
}

__global__ void scanC_kernel() {
    int i = blockIdx.x * blockDim.x + threadIdx.x;
    if (i >= NUM_NODES) return;
    int o = g_off[i] + g_bsum[i / SCAN_BLK];
    g_off[i] = o;
    g_deg[i] = o;
}

__global__ void fill_kernel(const int* __restrict__ ei32, int E) {
    int e = blockIdx.x * blockDim.x + threadIdx.x;
    if (e >= E) return;
    int s, d;
    if (g_is64) { s = ei32[2 * e]; d = ei32[2 * (E + e)]; }
    else        { s = ei32[e];     d = ei32[E + e]; }
    int pos = atomicAdd(&g_deg[d], 1);
    g_csrc[pos] = s;
}

// ---------------------------------------------------------------------------
// GEMM: C16[N,128](fp16) = act(A[N,128]) @ W[128,128]  — f32x2 packed FMA
// Block 256 threads, 64-row tile. Warp = 8 rows, lane = 4 cols.
// Epilogue converts to half2 pairs (8B per lane-row).
// ---------------------------------------------------------------------------
template <bool RELU>
__global__ void gemm128_kernel(const float* __restrict__ A, const float* __restrict__ W,
                               __half* __restrict__ C16, int N) {
    extern __shared__ float sm[];
    float* Ws = sm;              // 128*128
    float* As = sm + 128 * 128;  // 64*128

    const int tid = threadIdx.x;

    {
        const float4* W4 = (const float4*)W;
        float4* Ws4 = (float4*)Ws;
        #pragma unroll
        for (int i = 0; i < 16; i++) Ws4[tid + i * 256] = W4[tid + i * 256];
    }
    const int rowBase = blockIdx.x * 64;
    {
        const float4* A4 = (const float4*)A;
        float4* As4 = (float4*)As;
        #pragma unroll
        for (int i = 0; i < 8; i++) {
            int idx = tid + i * 256;
            int r = idx >> 5;
            int c4 = idx & 31;
            float4 v = make_float4(0.f, 0.f, 0.f, 0.f);
            if (rowBase + r < N) {
                v = A4[(size_t)(rowBase + r) * 32 + c4];
                if (RELU) {
                    v.x = fmaxf(v.x, 0.f); v.y = fmaxf(v.y, 0.f);
                    v.z = fmaxf(v.z, 0.f); v.w = fmaxf(v.w, 0.f);
                }
            }
            As4[idx] = v;
        }
    }
    __syncthreads();

    const int lane = tid & 31;
    const int warp = tid >> 5;

    unsigned long long acc2[8][2];
    #pragma unroll
    for (int r = 0; r < 8; r++) { acc2[r][0] = 0ull; acc2[r][1] = 0ull; }

    for (int k = 0; k < 128; k += 4) {
        float4 a[8];
        #pragma unroll
        for (int r = 0; r < 8; r++)
            a[r] = *(const float4*)(As + (warp * 8 + r) * 128 + k);

        unsigned long long wlo[4], whi[4];
        #pragma unroll
        for (int kk = 0; kk < 4; kk++) {
            const unsigned long long* wp =
                (const unsigned long long*)(Ws + (k + kk) * 128 + lane * 4);
            wlo[kk] = wp[0];
            whi[kk] = wp[1];
        }

        #pragma unroll
        for (int kk = 0; kk < 4; kk++) {
            #pragma unroll
            for (int r = 0; r < 8; r++) {
                float av = (kk == 0) ? a[r].x : (kk == 1) ? a[r].y
                         : (kk == 2) ? a[r].z : a[r].w;
                unsigned long long av2 = pack2(av, av);
                FMA2(acc2[r][0], av2, wlo[kk]);
                FMA2(acc2[r][1], av2, whi[kk]);
            }
        }
    }

    #pragma unroll
    for (int r = 0; r < 8; r++) {
        int row = rowBase + warp * 8 + r;
        if (row < N) {
            float4 o;
            unpack2(o.x, o.y, acc2[r][0]);
            unpack2(o.z, o.w, acc2[r][1]);
            __half2 h01 = __floats2half2_rn(o.x, o.y);
            __half2 h23 = __floats2half2_rn(o.z, o.w);
            uint2 pv;
            pv.x = *reinterpret_cast<uint32_t*>(&h01);
            pv.y = *reinterpret_cast<uint32_t*>(&h23);
            *(uint2*)(C16 + (size_t)row * 128 + lane * 4) = pv;
        }
    }
}

// ---------------------------------------------------------------------------
// GEMM: C[N,40] = relu(A[N,128]) @ W[128,40] — f32x2, one row per thread.
// (fp32 path — output-adjacent, keep full precision)
// ---------------------------------------------------------------------------
__global__ void gemm40_kernel(const float* __restrict__ A, const float* __restrict__ W,
                              float* __restrict__ C, int N) {
    __shared__ float Ws[128 * 40];
    for (int i = threadIdx.x; i < 128 * 40; i += blockDim.x) Ws[i] = W[i];
    __syncthreads();

    int row = blockIdx.x * blockDim.x + threadIdx.x;
    if (row >= N) return;

    unsigned long long acc2[20];
    #pragma unroll
    for (int j = 0; j < 20; j++) acc2[j] = 0ull;

    const float4* Arow = (const float4*)(A + (size_t)row * 128);
    for (int k4 = 0; k4 < 32; k4++) {
        float4 a = Arow[k4];
        a.x = fmaxf(a.x, 0.f); a.y = fmaxf(a.y, 0.f);
        a.z = fmaxf(a.z, 0.f); a.w = fmaxf(a.w, 0.f);
        #pragma unroll
        for (int kk = 0; kk < 4; kk++) {
            float av = (kk == 0) ? a.x : (kk == 1) ? a.y : (kk == 2) ? a.z : a.w;
            unsigned long long av2 = pack2(av, av);
            const unsigned long long* wrow =
                (const unsigned long long*)(Ws + (k4 * 4 + kk) * 40);
            #pragma unroll
            for (int j = 0; j < 20; j++) FMA2(acc2[j], av2, wrow[j]);
        }
    }

    unsigned long long* Co = (unsigned long long*)(C + (size_t)row * 40);
    #pragma unroll
    for (int j = 0; j < 20; j++) Co[j] = acc2[j];
}

// ---------------------------------------------------------------------------
// CSR gather (128 dims, fp16 messages): one warp per node, lane owns 4 cols.
// agg[n] = b + sum_{e in csr[n]} hw16[src[e]]   (fp32 accumulation)
// ---------------------------------------------------------------------------
__global__ void gather128_kernel(const __half* __restrict__ hw16,
                                 const float* __restrict__ b,
                                 float* __restrict__ agg) {
    int w = (blockIdx.x * blockDim.x + threadIdx.x) >> 5;
    int lane = threadIdx.x & 31;
    if (w >= NUM_NODES) return;
    int beg = __ldg(&g_off[w]);
    int end = __ldg(&g_off[w + 1]);

    float4 acc = *(const float4*)(b + lane * 4);
    int i = beg;
    for (; i + 4 <= end; i += 4) {
        int s0 = g_csrc[i], s1 = g_csrc[i + 1], s2 = g_csrc[i + 2], s3 = g_csrc[i + 3];
        uint2 u0 = *((const uint2*)(hw16 + (size_t)s0 * 128) + lane);
        uint2 u1 = *((const uint2*)(hw16 + (size_t)s1 * 128) + lane);
        uint2 u2 = *((const uint2*)(hw16 + (size_t)s2 * 128) + lane);
        uint2 u3 = *((const uint2*)(hw16 + (size_t)s3 * 128) + lane);
        float4 v0 = h8_to_f4(u0), v1 = h8_to_f4(u1);
        float4 v2 = h8_to_f4(u2), v3 = h8_to_f4(u3);
        acc.x += v0.x + v1.x + v2.x + v3.x;
        acc.y += v0.y + v1.y + v2.y + v3.y;
        acc.z += v0.z + v1.z + v2.z + v3.z;
        acc.w += v0.w + v1.w + v2.w + v3.w;
    }
    for (; i < end; i++) {
        int s = g_csrc[i];
        float4 v = h8_to_f4(*((const uint2*)(hw16 + (size_t)s * 128) + lane));
        acc.x += v.x; acc.y += v.y; acc.z += v.z; acc.w += v.w;
    }
    *(float4*)(agg + (size_t)w * 128 + lane * 4) = acc;
}

// ---------------------------------------------------------------------------
// CSR gather (40 dims, fp32): one warp per node, lanes 0..9 own a float4 each.
// ---------------------------------------------------------------------------
__global__ void gather40_kernel(const float* __restrict__ hw,
                                const float* __restrict__ b,
                                float* __restrict__ out) {
    int w = (blockIdx.x * blockDim.x + threadIdx.x) >> 5;
    int lane = threadIdx.x & 31;
    if (w >= NUM_NODES) return;
    int beg = __ldg(&g_off[w]);
    int end = __ldg(&g_off[w + 1]);

    float4 acc = make_float4(0.f, 0.f, 0.f, 0.f);
    if (lane < 10) acc = *(const float4*)(b + lane * 4);
    int i = beg;
    for (; i + 2 <= end; i += 2) {
        int s0 = g_csrc[i], s1 = g_csrc[i + 1];
        if (lane < 10) {
            float4 v0 = *(const float4*)(hw + (size_t)s0 * 40 + lane * 4);
            float4 v1 = *(const float4*)(hw + (size_t)s1 * 40 + lane * 4);
            acc.x += v0.x + v1.x; acc.y += v0.y + v1.y;
            acc.z += v0.z + v1.z; acc.w += v0.w + v1.w;
        }
    }
    for (; i < end; i++) {
        int s = g_csrc[i];
        if (lane < 10) {
            float4 v = *(const float4*)(hw + (size_t)s * 40 + lane * 4);
            acc.x += v.x; acc.y += v.y; acc.z += v.z; acc.w += v.w;
        }
    }
    if (lane < 10)
        *(float4*)(out + (size_t)w * 40 + lane * 4) = acc;
}

// ---------------------------------------------------------------------------
// Launch — round-7 structure (CSR on side stream over layer-0 GEMM),
// fp16 message buffers for the two 128-dim gathers.
// ---------------------------------------------------------------------------
extern "C" void kernel_launch(void* const* d_in, const int* in_sizes, int n_in,
                              void* d_out, int out_size) {
    const float* x  = (const float*)d_in[0];
    const int*   ei = (const int*)d_in[1];
    const float* W0 = (const float*)d_in[2];
    const float* b0 = (const float*)d_in[3];
    const float* W1 = (const float*)d_in[4];
    const float* b1 = (const float*)d_in[5];
    const float* W2 = (const float*)d_in[6];
    const float* b2 = (const float*)d_in[7];
    float* out = (float*)d_out;

    const int N = NUM_NODES, E = NUM_EDGES;

    __half* bufHW16;
    float *bufAGG, *bufO;
    cudaGetSymbolAddress((void**)&bufHW16, g_bufHW16);
    cudaGetSymbolAddress((void**)&bufAGG, g_bufAGG);
    cudaGetSymbolAddress((void**)&bufO, g_bufO);
    int* degPtr;
    cudaGetSymbolAddress((void**)&degPtr, g_deg);

    const int SMEM = (128 * 128 + 64 * 128) * sizeof(float);  // 96KB
    cudaFuncSetAttribute(gemm128_kernel<false>, cudaFuncAttributeMaxDynamicSharedMemorySize, SMEM);
    cudaFuncSetAttribute(gemm128_kernel<true>,  cudaFuncAttributeMaxDynamicSharedMemorySize, SMEM);

    static cudaStream_t s1 = nullptr;
    static cudaEvent_t evFork = nullptr, evCSR = nullptr;
    if (s1 == nullptr) {
        cudaStreamCreateWithFlags(&s1, cudaStreamNonBlocking);
        cudaEventCreateWithFlags(&evFork, cudaEventDisableTiming);
        cudaEventCreateWithFlags(&evCSR,  cudaEventDisableTiming);
    }

    // --- fork: CSR build on s1, layer-0 GEMM on main ---
    cudaEventRecord(evFork, 0);
    cudaStreamWaitEvent(s1, evFork, 0);

    detect_idx_dtype<<<1, 32, 0, s1>>>(ei);
    cudaMemsetAsync(degPtr, 0, NUM_NODES * sizeof(int), s1);
    hist_kernel<<<(E + 255) / 256, 256, 0, s1>>>(ei, E);
    scanA_kernel<<<SCAN_NBLOCKS, SCAN_BLK, 0, s1>>>();
    scanB_kernel<<<1, 128, 0, s1>>>();
    scanC_kernel<<<(N + 255) / 256, 256, 0, s1>>>();
    fill_kernel<<<(E + 255) / 256, 256, 0, s1>>>(ei, E);
    cudaEventRecord(evCSR, s1);

    gemm128_kernel<false><<<(N + 63) / 64, 256, SMEM>>>(x, W0, bufHW16, N);

    // --- join CSR ---
    cudaStreamWaitEvent(0, evCSR, 0);

    const int GWARP_BLOCKS = (N * 32 + 255) / 256;  // 1 warp per node

    // Layer 0 aggregate
    gather128_kernel<<<GWARP_BLOCKS, 256>>>(bufHW16, b0, bufAGG);

    // Layer 1
    gemm128_kernel<true><<<(N + 63) / 64, 256, SMEM>>>(bufAGG, W1, bufHW16, N);
    gather128_kernel<<<GWARP_BLOCKS, 256>>>(bufHW16, b1, bufAGG);

    // Layer 2 (fp32 end-to-end)
    gemm40_kernel<<<(N + 255) / 256, 256>>>(bufAGG, W2, bufO, N);
    gather40_kernel<<<GWARP_BLOCKS, 256>>>(bufO, b2, out);
}

// round 15
// speedup vs baseline: 1.2457x; 1.0715x over previous
#include <cuda_runtime.h>
#include <cuda_fp16.h>
#include <cstdint>

// Problem constants
#define NUM_NODES 50000
#define NUM_EDGES 800000
#define D_IN  128
#define D_HID 128
#define D_OUT 40

#define SCAN_BLK 512
#define SCAN_NBLOCKS ((NUM_NODES + SCAN_BLK - 1) / SCAN_BLK)   // 98

// Scratch buffers (device globals; no allocation allowed)
// hw (projected messages) fp16: 128 half = 256 B = 16 uint4 per node.
__device__ uint4 g_bufHW16[NUM_NODES * 16];    // fp16 messages (layers 0/1)
__device__ float g_bufAGG[NUM_NODES * D_HID];  // fp32 aggregation
__device__ uint2 g_bufO16[NUM_NODES * 10];     // fp16 layer-2 projections (40 half)
__device__ int   g_is64;                       // edge_index dtype flag
__device__ int   g_deg[NUM_NODES];             // degree counts, then fill cursor
__device__ int   g_off[NUM_NODES + 1];         // CSR row offsets (by dst)
__device__ int   g_csrc[NUM_EDGES];            // CSR source ids
__device__ int   g_bsum[SCAN_NBLOCKS];         // per-block scan partials

// ---------------------------------------------------------------------------
// f32x2 packed-FMA helpers (Blackwell dual-FP32 pipe, PTX-only)
// ---------------------------------------------------------------------------
__device__ __forceinline__ unsigned long long pack2(float x, float y) {
    unsigned long long r;
    asm("mov.b64 %0, {%1, %2};" : "=l"(r) : "f"(x), "f"(y));
    return r;
}
__device__ __forceinline__ void unpack2(float& x, float& y, unsigned long long v) {
    asm("mov.b64 {%0, %1}, %2;" : "=f"(x), "=f"(y) : "l"(v));
}
#define FMA2(d, a, b) \
    asm("fma.rn.f32x2 %0, %1, %2, %0;" : "+l"(d) : "l"(a), "l"(b))

// accumulate 8 fp16 (uint4) into acc[0..7]
__device__ __forceinline__ void addh8(float* acc, uint4 u) {
    __half2* h = (__half2*)&u;
    #pragma unroll
    for (int j = 0; j < 4; j++) {
        float2 f = __half22float2(h[j]);
        acc[2 * j]     += f.x;
        acc[2 * j + 1] += f.y;
    }
}
// accumulate 4 fp16 (uint2) into acc[0..3]
__device__ __forceinline__ void addh4(float* acc, uint2 u) {
    __half2 a = *reinterpret_cast<__half2*>(&u.x);
    __half2 b = *reinterpret_cast<__half2*>(&u.y);
    float2 fa = __half22float2(a);
    float2 fb = __half22float2(b);
    acc[0] += fa.x; acc[1] += fa.y; acc[2] += fb.x; acc[3] += fb.y;
}

// ---------------------------------------------------------------------------
// Detect whether edge_index is int64 (odd 32-bit words all zero) or int32.
// ---------------------------------------------------------------------------
__global__ void detect_idx_dtype(const int* __restrict__ ei32) {
    if (threadIdx.x == 0 && blockIdx.x == 0) {
        int is64 = 1;
        for (int i = 0; i < 256; i++) {
            if (ei32[2 * i + 1] != 0) { is64 = 0; break; }
        }
        g_is64 = is64;
    }
}

// ---------------------------------------------------------------------------
// CSR build: zero (memset) -> histogram(dst) -> 3-phase scan -> fill
// ---------------------------------------------------------------------------
__global__ void hist_kernel(const int* __restrict__ ei32, int E) {
    int e = blockIdx.x * blockDim.x + threadIdx.x;
    if (e >= E) return;
    int d = g_is64 ? ei32[2 * (E + e)] : ei32[E + e];
    atomicAdd(&g_deg[d], 1);
}

__global__ void scanA_kernel() {
    __shared__ int wsum[16];
    const int tid = threadIdx.x;
    const int lane = tid & 31, wid = tid >> 5;
    int i = blockIdx.x * SCAN_BLK + tid;
    int v = (i < NUM_NODES) ? g_deg[i] : 0;
    int x = v;
    #pragma unroll
    for (int s = 1; s < 32; s <<= 1) {
        int t = __shfl_up_sync(0xffffffffu, x, s);
        if (lane >= s) x += t;
    }
    if (lane == 31) wsum[wid] = x;
    __syncthreads();
    if (wid == 0 && lane < 16) {
        int y = wsum[lane];
        #pragma unroll
        for (int s = 1; s < 16; s <<= 1) {
            int t = __shfl_up_sync(0xffffu, y, s);
            if (lane >= s) y += t;
        }
        wsum[lane] = y;
    }
    __syncthreads();
    int warpoff = (wid == 0) ? 0 : wsum[wid - 1];
    if (i < NUM_NODES) g_off[i] = warpoff + x - v;
    if (tid == SCAN_BLK - 1) g_bsum[blockIdx.x] = wsum[15];
}

__global__ void scanB_kernel() {
    __shared__ int wsum[4];
    const int tid = threadIdx.x;     // 128 threads
    const int lane = tid & 31, wid = tid >> 5;
    int v = (tid < SCAN_NBLOCKS) ? g_bsum[tid] : 0;
    int x = v;
    #pragma unroll
    for (int s = 1; s < 32; s <<= 1) {
        int t = __shfl_up_sync(0xffffffffu, x, s);
        if (lane >= s) x += t;
    }
    if (lane == 31) wsum[wid] = x;
    __syncthreads();
    if (tid == 0) {
        int c = 0;
        #pragma unroll
        for (int k = 0; k < 4; k++) { int t = wsum[k]; wsum[k] = c; c += t; }
    }
    __syncthreads();
    int excl = wsum[wid] + x - v;
    if (tid < SCAN_NBLOCKS) g_bsum[tid] = excl;
    if (tid == 127) g_off[NUM_NODES] = excl + v;     // grand total (=E)
}

__global__ void scanC_kernel() {
    int i = blockIdx.x * blockDim.x + threadIdx.x;
    if (i >= NUM_NODES) return;
    int o = g_off[i] + g_bsum[i / SCAN_BLK];
    g_off[i] = o;
    g_deg[i] = o;
}

__global__ void fill_kernel(const int* __restrict__ ei32, int E) {
    int e = blockIdx.x * blockDim.x + threadIdx.x;
    if (e >= E) return;
    int s, d;
    if (g_is64) { s = ei32[2 * e]; d = ei32[2 * (E + e)]; }
    else        { s = ei32[e];     d = ei32[E + e]; }
    int pos = atomicAdd(&g_deg[d], 1);
    g_csrc[pos] = s;
}

// ---------------------------------------------------------------------------
// GEMM: C16[N,128](fp16) = act(A[N,128]) @ W[128,128]  — f32x2 packed FMA
// ---------------------------------------------------------------------------
template <bool RELU>
__global__ void gemm128_kernel(const float* __restrict__ A, const float* __restrict__ W,
                               __half* __restrict__ C16, int N) {
    extern __shared__ float sm[];
    float* Ws = sm;              // 128*128
    float* As = sm + 128 * 128;  // 64*128

    const int tid = threadIdx.x;

    {
        const float4* W4 = (const float4*)W;
        float4* Ws4 = (float4*)Ws;
        #pragma unroll
        for (int i = 0; i < 16; i++) Ws4[tid + i * 256] = W4[tid + i * 256];
    }
    const int rowBase = blockIdx.x * 64;
    {
        const float4* A4 = (const float4*)A;
        float4* As4 = (float4*)As;
        #pragma unroll
        for (int i = 0; i < 8; i++) {
            int idx = tid + i * 256;
            int r = idx >> 5;
            int c4 = idx & 31;
            float4 v = make_float4(0.f, 0.f, 0.f, 0.f);
            if (rowBase + r < N) {
                v = A4[(size_t)(rowBase + r) * 32 + c4];
                if (RELU) {
                    v.x = fmaxf(v.x, 0.f); v.y = fmaxf(v.y, 0.f);
                    v.z = fmaxf(v.z, 0.f); v.w = fmaxf(v.w, 0.f);
                }
            }
            As4[idx] = v;
        }
    }
    __syncthreads();

    const int lane = tid & 31;
    const int warp = tid >> 5;

    unsigned long long acc2[8][2];
    #pragma unroll
    for (int r = 0; r < 8; r++) { acc2[r][0] = 0ull; acc2[r][1] = 0ull; }

    for (int k = 0; k < 128; k += 4) {
        float4 a[8];
        #pragma unroll
        for (int r = 0; r < 8; r++)
            a[r] = *(const float4*)(As + (warp * 8 + r) * 128 + k);

        unsigned long long wlo[4], whi[4];
        #pragma unroll
        for (int kk = 0; kk < 4; kk++) {
            const unsigned long long* wp =
                (const unsigned long long*)(Ws + (k + kk) * 128 + lane * 4);
            wlo[kk] = wp[0];
            whi[kk] = wp[1];
        }

        #pragma unroll
        for (int kk = 0; kk < 4; kk++) {
            #pragma unroll
            for (int r = 0; r < 8; r++) {
                float av = (kk == 0) ? a[r].x : (kk == 1) ? a[r].y
                         : (kk == 2) ? a[r].z : a[r].w;
                unsigned long long av2 = pack2(av, av);
                FMA2(acc2[r][0], av2, wlo[kk]);
                FMA2(acc2[r][1], av2, whi[kk]);
            }
        }
    }

    #pragma unroll
    for (int r = 0; r < 8; r++) {
        int row = rowBase + warp * 8 + r;
        if (row < N) {
            float4 o;
            unpack2(o.x, o.y, acc2[r][0]);
            unpack2(o.z, o.w, acc2[r][1]);
            __half2 h01 = __floats2half2_rn(o.x, o.y);
            __half2 h23 = __floats2half2_rn(o.z, o.w);
            uint2 pv;
            pv.x = *reinterpret_cast<uint32_t*>(&h01);
            pv.y = *reinterpret_cast<uint32_t*>(&h23);
            *(uint2*)(C16 + (size_t)row * 128 + lane * 4) = pv;
        }
    }
}

// ---------------------------------------------------------------------------
// GEMM: C16[N,40](fp16) = relu(A[N,128]) @ W[128,40] — f32x2, one row/thread.
// ---------------------------------------------------------------------------
__global__ void gemm40_kernel(const float* __restrict__ A, const float* __restrict__ W,
                              __half* __restrict__ C16, int N) {
    __shared__ float Ws[128 * 40];
    for (int i = threadIdx.x; i < 128 * 40; i += blockDim.x) Ws[i] = W[i];
    __syncthreads();

    int row = blockIdx.x * blockDim.x + threadIdx.x;
    if (row >= N) return;

    unsigned long long acc2[20];
    #pragma unroll
    for (int j = 0; j < 20; j++) acc2[j] = 0ull;

    const float4* Arow = (const float4*)(A + (size_t)row * 128);
    for (int k4 = 0; k4 < 32; k4++) {
        float4 a = Arow[k4];
        a.x = fmaxf(a.x, 0.f); a.y = fmaxf(a.y, 0.f);
        a.z = fmaxf(a.z, 0.f); a.w = fmaxf(a.w, 0.f);
        #pragma unroll
        for (int kk = 0; kk < 4; kk++) {
            float av = (kk == 0) ? a.x : (kk == 1) ? a.y : (kk == 2) ? a.z : a.w;
            unsigned long long av2 = pack2(av, av);
            const unsigned long long* wrow =
                (const unsigned long long*)(Ws + (k4 * 4 + kk) * 40);
            #pragma unroll
            for (int j = 0; j < 20; j++) FMA2(acc2[j], av2, wrow[j]);
        }
    }

    uint32_t hv[20];
    #pragma unroll
    for (int j = 0; j < 20; j++) {
        float x, y;
        unpack2(x, y, acc2[j]);
        __half2 h = __floats2half2_rn(x, y);
        hv[j] = *reinterpret_cast<uint32_t*>(&h);
    }
    uint2* Co = (uint2*)(C16 + (size_t)row * 40);
    #pragma unroll
    for (int j = 0; j < 10; j++) Co[j] = make_uint2(hv[2 * j], hv[2 * j + 1]);
}

// ---------------------------------------------------------------------------
// CSR gather (128 dims, fp16): one warp per node; half-warps own alternate
// edges, lane loads uint4 (8 cols, 16B). Partner sums combined via shfl.
// agg[n] = b + sum hw16[src]   (fp32 accumulation)
// ---------------------------------------------------------------------------
__global__ void gather128_kernel(const __half* __restrict__ hw16,
                                 const float* __restrict__ b,
                                 float* __restrict__ agg) {
    int w = (blockIdx.x * blockDim.x + threadIdx.x) >> 5;
    int lane = threadIdx.x & 31;
    if (w >= NUM_NODES) return;
    const int half = lane >> 4;    // which edge of a pair
    const int hl = lane & 15;      // owns cols hl*8 .. hl*8+7
    int beg = __ldg(&g_off[w]);
    int end = __ldg(&g_off[w + 1]);

    float acc[8];
    #pragma unroll
    for (int j = 0; j < 8; j++) acc[j] = 0.f;

    int i = beg;
    for (; i + 4 <= end; i += 4) {
        int sA = g_csrc[i + half];
        int sB = g_csrc[i + 2 + half];
        uint4 uA = *((const uint4*)(hw16 + (size_t)sA * 128) + hl);
        uint4 uB = *((const uint4*)(hw16 + (size_t)sB * 128) + hl);
        addh8(acc, uA);
        addh8(acc, uB);
    }
    for (; i + 2 <= end; i += 2) {
        int s = g_csrc[i + half];
        addh8(acc, *((const uint4*)(hw16 + (size_t)s * 128) + hl));
    }
    if (i < end && half == 0) {
        int s = g_csrc[i];
        addh8(acc, *((const uint4*)(hw16 + (size_t)s * 128) + hl));
    }

    // combine partner half-warp
    #pragma unroll
    for (int j = 0; j < 8; j++)
        acc[j] += __shfl_down_sync(0xffffffffu, acc[j], 16);

    if (half == 0) {
        float4 b0 = *(const float4*)(b + hl * 8);
        float4 b1 = *(const float4*)(b + hl * 8 + 4);
        float* dst = agg + (size_t)w * 128 + hl * 8;
        *(float4*)dst = make_float4(acc[0] + b0.x, acc[1] + b0.y,
                                    acc[2] + b0.z, acc[3] + b0.w);
        *(float4*)(dst + 4) = make_float4(acc[4] + b1.x, acc[5] + b1.y,
                                          acc[6] + b1.z, acc[7] + b1.w);
    }
}

// ---------------------------------------------------------------------------
// CSR gather (40 dims, fp16): one warp per node; half-warps own alternate
// edges, lanes hl<10 load uint2 (4 cols). Combine via shfl; fp32 out.
// ---------------------------------------------------------------------------
__global__ void gather40_kernel(const __half* __restrict__ hw16,
                                const float* __restrict__ b,
                                float* __restrict__ out) {
    int w = (blockIdx.x * blockDim.x + threadIdx.x) >> 5;
    int lane = threadIdx.x & 31;
    if (w >= NUM_NODES) return;
    const int half = lane >> 4;
    const int hl = lane & 15;      // active if hl<10; owns cols hl*4..+4
    int beg = __ldg(&g_off[w]);
    int end = __ldg(&g_off[w + 1]);

    float acc[4] = {0.f, 0.f, 0.f, 0.f};

    int i = beg;
    for (; i + 4 <= end; i += 4) {
        int sA = g_csrc[i + half];
        int sB = g_csrc[i + 2 + half];
        if (hl < 10) {
            addh4(acc, *((const uint2*)(hw16 + (size_t)sA * 40) + hl));
            addh4(acc, *((const uint2*)(hw16 + (size_t)sB * 40) + hl));
        }
    }
    for (; i + 2 <= end; i += 2) {
        int s = g_csrc[i + half];
        if (hl < 10) addh4(acc, *((const uint2*)(hw16 + (size_t)s * 40) + hl));
    }
    if (i < end && half == 0 && hl < 10) {
        int s = g_csrc[i];
        addh4(acc, *((const uint2*)(hw16 + (size_t)s * 40) + hl));
    }

    #pragma unroll
    for (int j = 0; j < 4; j++)
        acc[j] += __shfl_down_sync(0xffffffffu, acc[j], 16);

    if (half == 0 && hl < 10) {
        float4 bv = *(const float4*)(b + hl * 4);
        *(float4*)(out + (size_t)w * 40 + hl * 4) =
            make_float4(acc[0] + bv.x, acc[1] + bv.y, acc[2] + bv.z, acc[3] + bv.w);
    }
}

// ---------------------------------------------------------------------------
// Launch — round-7 structure (CSR on side stream over layer-0 GEMM),
// fp16 message buffers for all three gathers.
// ---------------------------------------------------------------------------
extern "C" void kernel_launch(void* const* d_in, const int* in_sizes, int n_in,
                              void* d_out, int out_size) {
    const float* x  = (const float*)d_in[0];
    const int*   ei = (const int*)d_in[1];
    const float* W0 = (const float*)d_in[2];
    const float* b0 = (const float*)d_in[3];
    const float* W1 = (const float*)d_in[4];
    const float* b1 = (const float*)d_in[5];
    const float* W2 = (const float*)d_in[6];
    const float* b2 = (const float*)d_in[7];
    float* out = (float*)d_out;

    const int N = NUM_NODES, E = NUM_EDGES;

    __half *bufHW16, *bufO16;
    float* bufAGG;
    cudaGetSymbolAddress((void**)&bufHW16, g_bufHW16);
    cudaGetSymbolAddress((void**)&bufAGG, g_bufAGG);
    cudaGetSymbolAddress((void**)&bufO16, g_bufO16);
    int* degPtr;
    cudaGetSymbolAddress((void**)&degPtr, g_deg);

    const int SMEM = (128 * 128 + 64 * 128) * sizeof(float);  // 96KB
    cudaFuncSetAttribute(gemm128_kernel<false>, cudaFuncAttributeMaxDynamicSharedMemorySize, SMEM);
    cudaFuncSetAttribute(gemm128_kernel<true>,  cudaFuncAttributeMaxDynamicSharedMemorySize, SMEM);

    static cudaStream_t s1 = nullptr;
    static cudaEvent_t evFork = nullptr, evCSR = nullptr;
    if (s1 == nullptr) {
        cudaStreamCreateWithFlags(&s1, cudaStreamNonBlocking);
        cudaEventCreateWithFlags(&evFork, cudaEventDisableTiming);
        cudaEventCreateWithFlags(&evCSR,  cudaEventDisableTiming);
    }

    // --- fork: CSR build on s1, layer-0 GEMM on main ---
    cudaEventRecord(evFork, 0);
    cudaStreamWaitEvent(s1, evFork, 0);

    detect_idx_dtype<<<1, 32, 0, s1>>>(ei);
    cudaMemsetAsync(degPtr, 0, NUM_NODES * sizeof(int), s1);
    hist_kernel<<<(E + 255) / 256, 256, 0, s1>>>(ei, E);
    scanA_kernel<<<SCAN_NBLOCKS, SCAN_BLK, 0, s1>>>();
    scanB_kernel<<<1, 128, 0, s1>>>();
    scanC_kernel<<<(N + 255) / 256, 256, 0, s1>>>();
    fill_kernel<<<(E + 255) / 256, 256, 0, s1>>>(ei, E);
    cudaEventRecord(evCSR, s1);

    gemm128_kernel<false><<<(N + 63) / 64, 256, SMEM>>>(x, W0, bufHW16, N);

    // --- join CSR ---
    cudaStreamWaitEvent(0, evCSR, 0);

    const int GWARP_BLOCKS = (N * 32 + 255) / 256;  // 1 warp per node

    // Layer 0 aggregate
    gather128_kernel<<<GWARP_BLOCKS, 256>>>(bufHW16, b0, bufAGG);

    // Layer 1
    gemm128_kernel<true><<<(N + 63) / 64, 256, SMEM>>>(bufAGG, W1, bufHW16, N);
    gather128_kernel<<<GWARP_BLOCKS, 256>>>(bufHW16, b1, bufAGG);

    // Layer 2
    gemm40_kernel<<<(N + 255) / 256, 256>>>(bufAGG, W2, bufO16, N);
    gather40_kernel<<<GWARP_BLOCKS, 256>>>(bufO16, b2, out);
}